// round 1
// baseline (speedup 1.0000x reference)
#include <cuda_runtime.h>

// CSpace resonator bank as exact IIR recurrences.
// out[b, plane, t], planes: [0:64)=Re fwd, [64:128)=Im fwd, [128:192)=Re bwd, [192:256)=Im bwd.
// Forward:  y[t] = eig*y[t-1] + scale*x[t],      out = y
// Backward: z[t] = eig*z[t+1] + scale*x[t],      out = z
// eig = kernel[c,1]/kernel[c,0],  scale = kernel[c,0] = 1/norm  (kernel[c,0] is real).

#define T_LEN 48000
#define C_CH  64
#define B_SZ  8
#define KLEN  24000
#define P_CH  125   // active chunk threads (P_CH * L_CH == T_LEN)
#define L_CH  384   // chunk length
#define W_T   16    // tile width (output staging)
#define NT    (L_CH / W_T)   // 24 tiles per chunk
#define BT    128   // blockDim

__global__ __launch_bounds__(BT) void cspace_iir_kernel(
    const float* __restrict__ audio,   // (B, T)
    const float* __restrict__ kre,     // (C, KLEN)
    const float* __restrict__ kim,     // (C, KLEN)
    float* __restrict__ out)           // (B, 256, T)
{
    __shared__ float2 tile[BT][W_T + 1];  // stride 17 float2 = 34 words: bank-conflict-free
    __shared__ float2 seeds[BT];
    __shared__ float2 stin[BT];

    const int bid = blockIdx.x;        // 0..1023
    const int dir = bid & 1;
    const int c   = (bid >> 1) & (C_CH - 1);
    const int b   = bid >> 7;

    const int r = threadIdx.x;

    // Channel constants from the actual input kernels.
    const float k0    = kre[(size_t)c * KLEN];         // 1/norm (real)
    const float invk0 = 1.0f / k0;
    const float er    = kre[(size_t)c * KLEN + 1] * invk0;
    const float ei    = kim[(size_t)c * KLEN + 1] * invk0;
    const float scale = k0;

    const float* x = audio + (size_t)b * T_LEN;

    const bool active = (r < P_CH);
    const int p0 = r * L_CH;                 // flow-space start of this thread's chunk
    const int stp = dir ? -1 : 1;

    // ---------------- Pass 1: chunk-local end state (seed) ----------------
    float yr = 0.0f, yi = 0.0f;
    if (active) {
        const float* xp = dir ? (x + (T_LEN - 1 - p0)) : (x + p0);
        #pragma unroll 8
        for (int s = 0; s < L_CH; ++s) {
            float xs = (*xp) * scale;
            xp += stp;
            float nyr = fmaf(er, yr, fmaf(-ei, yi, xs));
            float nyi = fmaf(ei, yr, er * yi);
            yr = nyr; yi = nyi;
        }
    }
    seeds[r] = make_float2(yr, yi);
    __syncthreads();

    // ---------------- Serial combine: exact incoming state per chunk ------
    if (r == 0) {
        // eig^L_CH, L_CH = 384 = 3 * 2^7
        float t2r = fmaf(er, er, -ei * ei);
        float t2i = 2.0f * er * ei;
        float mr  = fmaf(t2r, er, -t2i * ei);   // eig^3
        float mi  = fmaf(t2r, ei,  t2i * er);
        #pragma unroll
        for (int q = 0; q < 7; ++q) {           // ^128
            float nr = fmaf(mr, mr, -mi * mi);
            float ni = 2.0f * mr * mi;
            mr = nr; mi = ni;
        }
        float sr = 0.0f, si = 0.0f;
        for (int j = 0; j < P_CH; ++j) {
            stin[j] = make_float2(sr, si);
            float2 e = seeds[j];
            float nsr = fmaf(mr, sr, fmaf(-mi, si, e.x));
            float nsi = fmaf(mi, sr, fmaf( mr, si, e.y));
            sr = nsr; si = nsi;
        }
    }
    __syncthreads();

    // ---------------- Pass 2: rescan with true state, staged writes -------
    float2 st = stin[r];
    yr = st.x; yi = st.y;
    const float* xp = dir ? (x + (T_LEN - 1 - p0)) : (x + p0);
    const int colxor = dir ? (W_T - 1) : 0;   // reversed in-tile placement for backward dir

    float* out_re = out + ((size_t)b * 256 + (size_t)dir * 128 + c) * T_LEN;
    float* out_im = out_re + (size_t)64 * T_LEN;

    for (int w = 0; w < NT; ++w) {
        if (active) {
            #pragma unroll
            for (int j = 0; j < W_T; ++j) {
                float xs = (*xp) * scale;
                xp += stp;
                float nyr = fmaf(er, yr, fmaf(-ei, yi, xs));
                float nyi = fmaf(ei, yr, er * yi);
                yr = nyr; yi = nyi;
                tile[r][j ^ colxor] = make_float2(yr, yi);
            }
        }
        __syncthreads();
        // Cooperative coalesced flush: contiguous, 64B-aligned 16-float runs.
        for (int k = threadIdx.x; k < P_CH * W_T; k += BT) {
            int row = k >> 4;           // W_T = 16
            int col = k & 15;
            int p0r = row * L_CH;
            int tlo = dir ? (T_LEN - p0r - (w + 1) * W_T) : (p0r + w * W_T);
            float2 v = tile[row][col];
            out_re[tlo + col] = v.x;
            out_im[tlo + col] = v.y;
        }
        __syncthreads();
    }
}

extern "C" void kernel_launch(void* const* d_in, const int* in_sizes, int n_in,
                              void* d_out, int out_size) {
    const float* audio = (const float*)d_in[0];
    const float* kre   = (const float*)d_in[1];
    const float* kim   = (const float*)d_in[2];
    float* out = (float*)d_out;
    cspace_iir_kernel<<<B_SZ * C_CH * 2, BT>>>(audio, kre, kim, out);
}

// round 2
// speedup vs baseline: 1.8685x; 1.8685x over previous
#include <cuda_runtime.h>

// CSpace resonator bank as exact IIR recurrences (two-pass chunked scan).
// out[b, plane, t], planes: [0:64)=Re fwd, [64:128)=Im fwd, [128:192)=Re bwd, [192:256)=Im bwd.
// eig = kernel[c,1]/kernel[c,0],  scale = kernel[c,0] = 1/norm (kernel[c,0] is real).
//
// R2 change vs R1: all audio reads go through coalesced shared-memory staging
// (R1 read audio with 384-float lane stride -> 32 L1 wavefronts per LDG; that
// was the 83.5% L1 bottleneck). Pass-2 flush is software-pipelined with the
// next tile's staging, and gmem stores are widened to STG.64.

#define T_LEN 48000
#define C_CH  64
#define B_SZ  8
#define KLEN  24000
#define P_CH  125   // active chunk threads (P_CH * L_CH == T_LEN)
#define L_CH  384   // chunk length per thread
#define W_T   16    // tile width
#define NT    (L_CH / W_T)   // 24 tiles
#define BT    128   // blockDim

__global__ __launch_bounds__(BT) void cspace_iir_kernel(
    const float* __restrict__ audio,   // (B, T)
    const float* __restrict__ kre,     // (C, KLEN)
    const float* __restrict__ kim,     // (C, KLEN)
    float* __restrict__ out)           // (B, 256, T)
{
    __shared__ float  xs[P_CH][W_T + 1];     // staged audio (flow order), 8.5 KB
    __shared__ float2 tile[P_CH][W_T + 1];   // staged output, 17 KB
    __shared__ float2 seeds[BT];
    __shared__ float2 stin[BT];

    const int bid = blockIdx.x;        // 0..1023
    const int dir = bid & 1;
    const int c   = (bid >> 1) & (C_CH - 1);
    const int b   = bid >> 7;

    const int r   = threadIdx.x;
    const bool active = (r < P_CH);

    // Channel constants from the actual input kernels.
    const float k0    = kre[(size_t)c * KLEN];         // 1/norm (real)
    const float invk0 = 1.0f / k0;
    const float er    = kre[(size_t)c * KLEN + 1] * invk0;
    const float ei    = kim[(size_t)c * KLEN + 1] * invk0;
    const float scale = k0;

    const float* x = audio + (size_t)b * T_LEN;

    // ---------------- Pass 1: chunk-local end state (seed), tiled ---------
    float yr = 0.0f, yi = 0.0f;
    for (int w = 0; w < NT; ++w) {
        // coalesced stage of this tile's 125 x 16 audio samples (flow order)
        #pragma unroll
        for (int k = r; k < P_CH * W_T; k += BT) {
            int row = k >> 4, col = k & 15;
            int p = row * L_CH + w * W_T + col;          // flow-space index
            int t = dir ? (T_LEN - 1 - p) : p;
            xs[row][col] = x[t];
        }
        __syncthreads();
        if (active) {
            #pragma unroll
            for (int j = 0; j < W_T; ++j) {
                float xv = xs[r][j] * scale;
                float nyr = fmaf(er, yr, fmaf(-ei, yi, xv));
                float nyi = fmaf(ei, yr, er * yi);
                yr = nyr; yi = nyi;
            }
        }
        __syncthreads();
    }
    seeds[r] = make_float2(yr, yi);
    __syncthreads();

    // ---------------- Serial combine: exact incoming state per chunk ------
    if (r == 0) {
        // eig^L_CH, L_CH = 384 = 3 * 2^7
        float t2r = fmaf(er, er, -ei * ei);
        float t2i = 2.0f * er * ei;
        float mr  = fmaf(t2r, er, -t2i * ei);   // eig^3
        float mi  = fmaf(t2r, ei,  t2i * er);
        #pragma unroll
        for (int q = 0; q < 7; ++q) {           // ^128
            float nr = fmaf(mr, mr, -mi * mi);
            float ni = 2.0f * mr * mi;
            mr = nr; mi = ni;
        }
        float sr = 0.0f, si = 0.0f;
        for (int j = 0; j < P_CH; ++j) {
            stin[j] = make_float2(sr, si);
            float2 e = seeds[j];
            float nsr = fmaf(mr, sr, fmaf(-mi, si, e.x));
            float nsi = fmaf(mi, sr, fmaf( mr, si, e.y));
            sr = nsr; si = nsi;
        }
    }
    __syncthreads();

    // ---------------- Pass 2: rescan with true state, staged I/O ----------
    float2 st = stin[r];
    yr = st.x; yi = st.y;
    const int colxor = dir ? (W_T - 1) : 0;   // in-tile time-ascending placement

    float* out_re = out + ((size_t)b * 256 + (size_t)dir * 128 + c) * T_LEN;
    float* out_im = out_re + (size_t)64 * T_LEN;

    for (int w = 0; w < NT; ++w) {
        // stage audio tile w (coalesced)
        #pragma unroll
        for (int k = r; k < P_CH * W_T; k += BT) {
            int row = k >> 4, col = k & 15;
            int p = row * L_CH + w * W_T + col;
            int t = dir ? (T_LEN - 1 - p) : p;
            xs[row][col] = x[t];
        }
        // flush tile w-1 (overlapped with staging, before the barrier)
        if (w > 0) {
            int wp = w - 1;
            #pragma unroll
            for (int k = r; k < P_CH * (W_T / 2); k += BT) {   // 2-float granules
                int row = k >> 3;
                int c2  = (k & 7) * 2;
                int tlo = dir ? (T_LEN - row * L_CH - (wp + 1) * W_T)
                              : (row * L_CH + wp * W_T);
                float2 a = tile[row][c2];
                float2 bb = tile[row][c2 + 1];
                *(float2*)&out_re[tlo + c2] = make_float2(a.x, bb.x);
                *(float2*)&out_im[tlo + c2] = make_float2(a.y, bb.y);
            }
        }
        __syncthreads();
        // compute tile w into 'tile'
        if (active) {
            #pragma unroll
            for (int j = 0; j < W_T; ++j) {
                float xv = xs[r][j] * scale;
                float nyr = fmaf(er, yr, fmaf(-ei, yi, xv));
                float nyi = fmaf(ei, yr, er * yi);
                yr = nyr; yi = nyi;
                tile[r][j ^ colxor] = make_float2(yr, yi);
            }
        }
        __syncthreads();
    }
    // final flush (tile NT-1)
    {
        int wp = NT - 1;
        #pragma unroll
        for (int k = r; k < P_CH * (W_T / 2); k += BT) {
            int row = k >> 3;
            int c2  = (k & 7) * 2;
            int tlo = dir ? (T_LEN - row * L_CH - (wp + 1) * W_T)
                          : (row * L_CH + wp * W_T);
            float2 a = tile[row][c2];
            float2 bb = tile[row][c2 + 1];
            *(float2*)&out_re[tlo + c2] = make_float2(a.x, bb.x);
            *(float2*)&out_im[tlo + c2] = make_float2(a.y, bb.y);
        }
    }
}

extern "C" void kernel_launch(void* const* d_in, const int* in_sizes, int n_in,
                              void* d_out, int out_size) {
    const float* audio = (const float*)d_in[0];
    const float* kre   = (const float*)d_in[1];
    const float* kim   = (const float*)d_in[2];
    float* out = (float*)d_out;
    cspace_iir_kernel<<<B_SZ * C_CH * 2, BT>>>(audio, kre, kim, out);
}

// round 3
// speedup vs baseline: 2.9602x; 1.5843x over previous
#include <cuda_runtime.h>

// CSpace resonator bank as exact IIR recurrences (two-pass chunked scan).
// out[b, plane, t]: [0:64)=Re fwd, [64:128)=Im fwd, [128:192)=Re bwd, [192:256)=Im bwd.
// eig = kernel[c,1]/kernel[c,0],  scale = kernel[c,0] (real).
//
// R3 vs R2: fully 4-wide vectorized smem staging/compute/flush (LDG.128/STS.128/
// LDS.128/STG.128, stride-20 rows = conflict-free), direction as a template
// parameter (two launches), Kogge-Stone parallel seed combine.

#define T_LEN 48000
#define C_CH  64
#define B_SZ  8
#define KLEN  24000
#define P_CH  125          // chunks (active threads)
#define L_CH  384          // chunk length per thread
#define W_T   16           // tile width (time samples)
#define NT    (L_CH / W_T) // 24 tiles
#define BT    128          // blockDim
#define XS_S  20           // row stride in floats (16B-aligned, conflict-free)

template<int DIR>
__global__ __launch_bounds__(BT) void cspace_iir_kernel(
    const float* __restrict__ audio,   // (B, T)
    const float* __restrict__ kre,     // (C, KLEN)
    const float* __restrict__ kim,     // (C, KLEN)
    float* __restrict__ out)           // (B, 256, T)
{
    __shared__ float  xs [P_CH][XS_S];   // staged audio, time order
    __shared__ float  tre[P_CH][XS_S];   // staged output Re, time order
    __shared__ float  tim[P_CH][XS_S];   // staged output Im, time order
    __shared__ float2 scanA[BT], scanB[BT];

    const int bid = blockIdx.x;          // 0..511
    const int c   = bid & (C_CH - 1);
    const int b   = bid >> 6;
    const int r   = threadIdx.x;
    const bool active = (r < P_CH);

    // Channel constants from the input kernels.
    const float k0    = kre[(size_t)c * KLEN];
    const float invk0 = 1.0f / k0;
    const float er    = kre[(size_t)c * KLEN + 1] * invk0;
    const float ei    = kim[(size_t)c * KLEN + 1] * invk0;
    const float scale = k0;

    const float* x = audio + (size_t)b * T_LEN;

    // Time-order base of (row, tile): 16 contiguous, 64B-aligned floats.
    auto tbase = [&](int row, int w) {
        return DIR ? (T_LEN - W_T - row * L_CH - w * W_T)
                   : (row * L_CH + w * W_T);
    };

    // ---------------- Pass 1: chunk-local end state (seed) ----------------
    float yr = 0.0f, yi = 0.0f;
    for (int w = 0; w < NT; ++w) {
        #pragma unroll
        for (int q = r; q < P_CH * 4; q += BT) {       // 500 float4 segments
            int row = q >> 2, c4 = q & 3;
            float4 v = *(const float4*)&x[tbase(row, w) + c4 * 4];
            *(float4*)&xs[row][c4 * 4] = v;
        }
        __syncthreads();
        if (active) {
            #pragma unroll
            for (int c4 = 0; c4 < 4; ++c4) {
                const int cc = DIR ? 3 - c4 : c4;       // flow order
                float4 xv = *(const float4*)&xs[r][cc * 4];
                float xa[4] = {xv.x, xv.y, xv.z, xv.w};
                #pragma unroll
                for (int k = 0; k < 4; ++k) {
                    float xvv = xa[DIR ? 3 - k : k] * scale;
                    float nyr = fmaf(er, yr, fmaf(-ei, yi, xvv));
                    float nyi = fmaf(ei, yr, er * yi);
                    yr = nyr; yi = nyi;
                }
            }
        }
        __syncthreads();
    }

    // ---------------- Kogge-Stone combine: incoming state per chunk -------
    // M = eig^384 = ((eig^3) squared 7 times)
    float t2r = fmaf(er, er, -ei * ei);
    float t2i = 2.0f * er * ei;
    float mr  = fmaf(t2r, er, -t2i * ei);
    float mi  = fmaf(t2r, ei,  t2i * er);
    #pragma unroll
    for (int q = 0; q < 7; ++q) {
        float nr = fmaf(mr, mr, -mi * mi);
        float ni = 2.0f * mr * mi;
        mr = nr; mi = ni;
    }
    scanA[r] = active ? make_float2(yr, yi) : make_float2(0.0f, 0.0f);
    __syncthreads();
    {
        float fr = mr, fi = mi;
        float2* src = scanA; float2* dst = scanB;
        #pragma unroll
        for (int d = 1; d < BT; d <<= 1) {
            float2 v = src[r];
            if (r >= d) {
                float2 u = src[r - d];
                float nvx = fmaf(fr, u.x, fmaf(-fi, u.y, v.x));
                float nvy = fmaf(fi, u.x, fmaf( fr, u.y, v.y));
                v.x = nvx; v.y = nvy;
            }
            dst[r] = v;
            float nfr = fmaf(fr, fr, -fi * fi);
            fi = 2.0f * fr * fi; fr = nfr;
            __syncthreads();
            float2* tmp = src; src = dst; dst = tmp;
        }
        float2 st = (r > 0) ? src[r - 1] : make_float2(0.0f, 0.0f);
        yr = st.x; yi = st.y;
    }

    // ---------------- Pass 2: rescan with true state, staged I/O ----------
    float* out_re = out + ((size_t)b * 256 + (size_t)DIR * 128 + c) * T_LEN;
    float* out_im = out_re + (size_t)64 * T_LEN;

    for (int w = 0; w < NT; ++w) {
        // stage audio tile w (vector, coalesced)
        #pragma unroll
        for (int q = r; q < P_CH * 4; q += BT) {
            int row = q >> 2, c4 = q & 3;
            float4 v = *(const float4*)&x[tbase(row, w) + c4 * 4];
            *(float4*)&xs[row][c4 * 4] = v;
        }
        // flush tile w-1 (overlapped with staging)
        if (w > 0) {
            #pragma unroll
            for (int q = r; q < P_CH * 4; q += BT) {
                int row = q >> 2, c4 = q & 3;
                int tb = tbase(row, w - 1) + c4 * 4;
                *(float4*)&out_re[tb] = *(const float4*)&tre[row][c4 * 4];
                *(float4*)&out_im[tb] = *(const float4*)&tim[row][c4 * 4];
            }
        }
        __syncthreads();
        // compute tile w into tre/tim (time order)
        if (active) {
            #pragma unroll
            for (int c4 = 0; c4 < 4; ++c4) {
                const int cc = DIR ? 3 - c4 : c4;
                float4 xv = *(const float4*)&xs[r][cc * 4];
                float xa[4] = {xv.x, xv.y, xv.z, xv.w};
                float orr[4], oii[4];
                #pragma unroll
                for (int k = 0; k < 4; ++k) {
                    float xvv = xa[DIR ? 3 - k : k] * scale;
                    float nyr = fmaf(er, yr, fmaf(-ei, yi, xvv));
                    float nyi = fmaf(ei, yr, er * yi);
                    yr = nyr; yi = nyi;
                    orr[DIR ? 3 - k : k] = yr;      // back to time order
                    oii[DIR ? 3 - k : k] = yi;
                }
                *(float4*)&tre[r][cc * 4] = make_float4(orr[0], orr[1], orr[2], orr[3]);
                *(float4*)&tim[r][cc * 4] = make_float4(oii[0], oii[1], oii[2], oii[3]);
            }
        }
        __syncthreads();
    }
    // final flush (tile NT-1)
    #pragma unroll
    for (int q = r; q < P_CH * 4; q += BT) {
        int row = q >> 2, c4 = q & 3;
        int tb = tbase(row, NT - 1) + c4 * 4;
        *(float4*)&out_re[tb] = *(const float4*)&tre[row][c4 * 4];
        *(float4*)&out_im[tb] = *(const float4*)&tim[row][c4 * 4];
    }
}

extern "C" void kernel_launch(void* const* d_in, const int* in_sizes, int n_in,
                              void* d_out, int out_size) {
    const float* audio = (const float*)d_in[0];
    const float* kre   = (const float*)d_in[1];
    const float* kim   = (const float*)d_in[2];
    float* out = (float*)d_out;
    cspace_iir_kernel<0><<<B_SZ * C_CH, BT>>>(audio, kre, kim, out);
    cspace_iir_kernel<1><<<B_SZ * C_CH, BT>>>(audio, kre, kim, out);
}